// round 16
// baseline (speedup 1.0000x reference)
#include <cuda_runtime.h>
#include <cuda_bf16.h>
#include <math.h>

// Problem constants (fixed by setup_inputs)
#define BB 16
#define NN 8400
#define CC 80
#define MM 64
#define RR 16
#define KTOP 13
#define NEG_INFF (-1e30f)

static constexpr int CAP2  = 576;                     // >= max rect candidates (531)
static constexpr int NTHR  = BB * MM;                 // 1024 threshold blocks
static constexpr int RPB   = 64;                      // rows per softplus block
static constexpr int NBSP  = (NN + RPB - 1) / RPB;    // 132 softplus blocks per b
static constexpr int T2    = 256;                     // threads/anchors per main block
static constexpr int NB2   = (NN + T2 - 1) / T2;      // 33

// ---------------- scratch (static device globals; no allocations) ----------
__device__ unsigned long long g_best[BB * NN];        // (align_bits<<32)|(63-m); 0 = no fg
__device__ float              g_mx[BB * NN];          // sigmoid(max valid logit) or NEG_INF
__device__ float              g_spb[BB * NBSP];       // per-block softplus partials
__device__ float              g_p2[BB * NB2 * 8];     // per-block loss partials

// ---------------- bit-exact helpers (selection path) -------------------------
__device__ __forceinline__ float iou_sel(float4 a, float4 b) {
    float x1 = fmaxf(a.x, b.x), y1 = fmaxf(a.y, b.y);
    float x2 = fminf(a.z, b.z), y2 = fminf(a.w, b.w);
    float iw = fmaxf(__fsub_rn(x2, x1), 0.f);
    float ih = fmaxf(__fsub_rn(y2, y1), 0.f);
    float inter = __fmul_rn(iw, ih);
    float a1 = __fmul_rn(__fsub_rn(a.z, a.x), __fsub_rn(a.w, a.y));
    float a2 = __fmul_rn(__fsub_rn(b.z, b.x), __fsub_rn(b.w, b.y));
    float den = __fadd_rn(__fsub_rn(__fadd_rn(a1, a2), inter), 1e-7f);
    return __fdiv_rn(inter, den);
}

__device__ __forceinline__ float sigmoid_sel(float x) {
    return __fdiv_rn(1.f, __fadd_rn(1.f, expf(-x)));
}

__device__ __forceinline__ float align_sel(float cls, float iou) {
    float i2 = __fmul_rn(iou, iou);
    float i4 = __fmul_rn(i2, i2);
    float i6 = __fmul_rn(i4, i2);
    return __fmul_rn(cls, i6);
}

// Sortable key matching jax.lax.top_k semantics: value desc, index asc on ties.
__device__ __forceinline__ unsigned long long pack_key(float v, int n) {
    unsigned int u = __float_as_uint(v);
    u = (u & 0x80000000u) ? ~u : (u | 0x80000000u);
    return ((unsigned long long)u << 32) | (unsigned int)(0xFFFFFFFFu - (unsigned int)n);
}

__device__ __forceinline__ bool mask_at(const unsigned char* cm, bool wide, int idx) {
    return wide ? (((const unsigned int*)cm)[idx] != 0u) : (cm[idx] != 0);
}

__device__ __forceinline__ unsigned long long umax64(unsigned long long a, unsigned long long b) {
    return a > b ? a : b;
}

__device__ __forceinline__ float ex2a(float x) {
    float r; asm("ex2.approx.ftz.f32 %0, %1;" : "=f"(r) : "f"(x)); return r;
}
__device__ __forceinline__ float lg2a(float x) {
    float r; asm("lg2.approx.ftz.f32 %0, %1;" : "=f"(r) : "f"(x)); return r;
}

// softplus in log2 domain; valid for |t| < ~120 (inputs are N(0,1) logits).
__device__ __forceinline__ float sp2(float t) {
    return lg2a(1.f + ex2a(t));
}

// order-preserving float<->uint for smem atomicMax
__device__ __forceinline__ unsigned int fenc(float v) {
    unsigned int u = __float_as_uint(v);
    return (u & 0x80000000u) ? ~u : (u | 0x80000000u);
}
__device__ __forceinline__ float fdec(unsigned int u) {
    return __uint_as_float((u & 0x80000000u) ? (u ^ 0x80000000u) : ~u);
}

// ---------------- K1: thresholds + fg-scatter (role A) | softplus (role B) ---
__global__ void __launch_bounds__(256)
k_pre(const float* __restrict__ ps, const float* __restrict__ pb,
      const int* __restrict__ gtl, const float* __restrict__ gtb,
      const unsigned char* __restrict__ cm) {
    const int tid = threadIdx.x, lane = tid & 31, warp = tid >> 5;
    const float L2E = 1.4426950408889634f;

    __shared__ float4 sbox_s;
    __shared__ int    slc, svalid, scnt, stot;
    __shared__ int    srect[3 * 5];
    __shared__ unsigned long long skeys[CAP2];
    __shared__ unsigned long long swtop[8 * KTOP];
    __shared__ unsigned long long s_thr;
    __shared__ float  svcB[CC];
    __shared__ int    sAllv, sAnyv;
    __shared__ float  spw[8];
    __shared__ unsigned int srmax[RPB];

    if (blockIdx.x < NTHR) {
        // ====== role A: per-(b,m) 13th-largest key + scatter selected ========
        const int b = blockIdx.x >> 6, m = blockIdx.x & 63;

        if (tid == 0) {
            const float* g = gtb + (b * MM + m) * 4;
            float4 bx = make_float4(g[0], g[1], g[2], g[3]);
            sbox_s = bx;
            int l  = gtl[b * MM + m];
            int lc = min(max(l, 0), CC - 1);
            slc = lc;
            const bool wide = (cm[1] == 0);
            svalid = (l >= 0 && l < CC && mask_at(cm, wide, b * CC + lc)) ? 1 : 0;
            scnt = 0;
            const int   nsL[3] = {80, 40, 20};
            const float ssL[3] = {8.f, 16.f, 32.f};
            int base = 0;
            for (int lv = 0; lv < 3; lv++) {
                int nl = nsL[lv]; float sl = ssL[lv];
                int x0 = max(0,      (int)floorf(bx.x / sl - 0.5f) - 1);
                int x1 = min(nl - 1, (int)ceilf (bx.z / sl - 0.5f) + 1);
                int y0 = max(0,      (int)floorf(bx.y / sl - 0.5f) - 1);
                int y1 = min(nl - 1, (int)ceilf (bx.w / sl - 0.5f) + 1);
                int cw = max(0, x1 - x0 + 1), ch = max(0, y1 - y0 + 1);
                srect[lv * 5 + 0] = x0; srect[lv * 5 + 1] = y0;
                srect[lv * 5 + 2] = cw; srect[lv * 5 + 3] = ch;
                srect[lv * 5 + 4] = base;
                base += cw * ch;
            }
            stot = base;
        }
        __syncthreads();

        if (svalid) {
            const float4 box = sbox_s;
            const int lc = slc;
            const int tot = stot;
            for (int idx = tid; idx < tot; idx += 256) {
                int lv = (idx >= srect[9]) ? ((idx >= srect[14]) ? 2 : 1) : 0;
                int loc = idx - srect[lv * 5 + 4];
                int cw  = srect[lv * 5 + 2];
                int iy  = loc / cw, ix = loc - iy * cw;
                ix += srect[lv * 5 + 0]; iy += srect[lv * 5 + 1];
                int nl, off; float sl;
                if (lv == 0)      { nl = 80; sl = 8.f;  off = 0;    }
                else if (lv == 1) { nl = 40; sl = 16.f; off = 6400; }
                else              { nl = 20; sl = 32.f; off = 8000; }
                float ax = (ix + 0.5f) * sl;   // bit-identical to input anchor grid
                float ay = (iy + 0.5f) * sl;
                if (ax >= box.x && ax <= box.z && ay >= box.y && ay <= box.w) {
                    int n = off + iy * nl + ix;
                    float4 pbox = __ldg((const float4*)(pb + ((size_t)b * NN + n) * 4));
                    float cls = sigmoid_sel(__ldg(ps + ((size_t)b * NN + n) * CC + lc));
                    float al  = align_sel(cls, iou_sel(pbox, box));
                    int slot = atomicAdd(&scnt, 1);
                    if (slot < CAP2) skeys[slot] = pack_key(al, n);
                }
            }
        }
        __syncthreads();

        const int c = min(scnt, CAP2);
        {
            const int chunk = (c + 7) >> 3;
            const int beg = warp * chunk;
            const int end = min(c, beg + chunk);
            unsigned long long k0 = 0, k1 = 0, k2 = 0;
            int i = beg + lane;
            if (i < end) k0 = skeys[i]; i += 32;
            if (i < end) k1 = skeys[i]; i += 32;
            if (i < end) k2 = skeys[i];
            for (int r = 0; r < KTOP; r++) {
                unsigned long long cur = umax64(k0, umax64(k1, k2));
                unsigned long long mx = cur;
#pragma unroll
                for (int o = 16; o; o >>= 1)
                    mx = umax64(mx, __shfl_xor_sync(0xFFFFFFFFu, mx, o));
                unsigned int bal = __ballot_sync(0xFFFFFFFFu, cur == mx);
                int leader = __ffs(bal) - 1;
                if (lane == leader) {
                    if (k0 == mx) k0 = 0; else if (k1 == mx) k1 = 0; else k2 = 0;
                }
                if (lane == 0) swtop[warp * KTOP + r] = mx;
            }
        }
        __syncthreads();
        if (warp == 0) {
            unsigned long long k0 = 0, k1 = 0, k2 = 0, k3 = 0;
            if (lane      < 8 * KTOP) k0 = swtop[lane];
            if (lane + 32 < 8 * KTOP) k1 = swtop[lane + 32];
            if (lane + 64 < 8 * KTOP) k2 = swtop[lane + 64];
            if (lane + 96 < 8 * KTOP) k3 = swtop[lane + 96];
            unsigned long long thr = 0;
            for (int r = 0; r < KTOP; r++) {
                unsigned long long cur = umax64(umax64(k0, k1), umax64(k2, k3));
                unsigned long long mx = cur;
#pragma unroll
                for (int o = 16; o; o >>= 1)
                    mx = umax64(mx, __shfl_xor_sync(0xFFFFFFFFu, mx, o));
                unsigned int bal = __ballot_sync(0xFFFFFFFFu, cur == mx);
                int leader = __ffs(bal) - 1;
                if (lane == leader) {
                    if (k0 == mx) k0 = 0; else if (k1 == mx) k1 = 0;
                    else if (k2 == mx) k2 = 0; else k3 = 0;
                }
                thr = mx;
            }
            if (lane == 0) s_thr = thr;    // 0 when <13 candidates: select all
        }
        __syncthreads();

        // scatter selected candidates: align>=0 so slot!=0 <=> fg
        {
            const unsigned long long thr = s_thr;
            const unsigned long long mtag = (unsigned long long)(MM - 1 - m);
            for (int i = tid; i < c; i += 256) {
                unsigned long long k = skeys[i];
                if (k >= thr && k != 0ull) {
                    unsigned int n = 0xFFFFFFFFu - (unsigned int)(k & 0xFFFFFFFFu);
                    unsigned long long sv = (k & 0xFFFFFFFF00000000ull) | mtag;
                    atomicMax(&g_best[b * NN + n], sv);
                }
            }
        }
    } else {
        // ====== role B: flat-coalesced softplus sum + per-row valid max ======
        const int i = blockIdx.x - NTHR;
        const int b = i / NBSP, blk = i - b * NBSP;
        const int row0 = blk * RPB;
        const int nrows = min(RPB, NN - row0);
        const int nf4 = nrows * 20;            // float4 count (20 per row)
        const bool wide = (cm[1] == 0);

        if (tid < CC) svcB[tid] = mask_at(cm, wide, b * CC + tid) ? 1.f : 0.f;
        if (tid < RPB) srmax[tid] = 0u;        // below all encoded reals
        __syncthreads();
        if (tid == 0) {
            float vs = 0.f;
            for (int cc = 0; cc < CC; cc++) vs += svcB[cc];
            sAllv = (vs == (float)CC) ? 1 : 0;
            sAnyv = (vs > 0.f) ? 1 : 0;
        }
        __syncthreads();

        const float4* base = (const float4*)(ps + ((size_t)b * NN + row0) * CC);
        float sp_l = 0.f;
        if (sAllv) {
#pragma unroll
            for (int it = 0; it < 5; it++) {
                int f = it * 256 + tid;
                if (f < nf4) {
                    float4 q = __ldg(base + f);
                    int r = f / 20;            // const-div -> mul/shift
                    float t0 = q.x * L2E, t1 = q.y * L2E;
                    float t2 = q.z * L2E, t3 = q.w * L2E;
                    sp_l += sp2(t0) + sp2(t1) + sp2(t2) + sp2(t3);
                    float mv = fmaxf(fmaxf(t0, t1), fmaxf(t2, t3));
                    atomicMax(&srmax[r], fenc(mv));
                }
            }
        } else {
#pragma unroll
            for (int it = 0; it < 5; it++) {
                int f = it * 256 + tid;
                if (f < nf4) {
                    float4 q = __ldg(base + f);
                    int r = f / 20;
                    int c0 = (f - r * 20) * 4;
                    float v0 = svcB[c0], v1 = svcB[c0 + 1];
                    float v2 = svcB[c0 + 2], v3 = svcB[c0 + 3];
                    float t0 = q.x * L2E, t1 = q.y * L2E;
                    float t2 = q.z * L2E, t3 = q.w * L2E;
                    sp_l += v0 * sp2(t0) + v1 * sp2(t1) + v2 * sp2(t2) + v3 * sp2(t3);
                    float m0 = (v0 != 0.f) ? t0 : -3.4e38f;
                    float m1 = (v1 != 0.f) ? t1 : -3.4e38f;
                    float m2 = (v2 != 0.f) ? t2 : -3.4e38f;
                    float m3 = (v3 != 0.f) ? t3 : -3.4e38f;
                    float mv = fmaxf(fmaxf(m0, m1), fmaxf(m2, m3));
                    atomicMax(&srmax[r], fenc(mv));
                }
            }
        }
        __syncthreads();

        // per-row mx -> g_mx (coalesced)
        if (tid < nrows) {
            float tm = fdec(srmax[tid]);
            g_mx[b * NN + row0 + tid] = sAnyv ? (1.f / (1.f + ex2a(-tm))) : NEG_INFF;
        }

        // block sum of sp_l
        float s = sp_l;
#pragma unroll
        for (int o = 16; o; o >>= 1) s += __shfl_down_sync(0xFFFFFFFFu, s, o);
        if (lane == 0) spw[warp] = s;
        __syncthreads();
        if (tid == 0) {
            float tot = 0.f;
#pragma unroll
            for (int w = 0; w < 8; w++) tot += spw[w];
            g_spb[i] = tot * (1.f / L2E);
        }
    }
}

// ---------------- K2: per-anchor fg losses (NO completion protocol) ----------
__global__ void __launch_bounds__(T2)
k_main(const float* __restrict__ ps, const float* __restrict__ pb,
       const float* __restrict__ ap, const float* __restrict__ st,
       const int* __restrict__ gtl, const float* __restrict__ gtb,
       const float* __restrict__ bd, const unsigned char* __restrict__ cm) {
    const int b    = blockIdx.y;
    const int tile = blockIdx.x * T2;
    const int tid  = threadIdx.x;
    const int warp = tid >> 5, lane = tid & 31;
    const bool wide = (cm[1] == 0);

    __shared__ float4 sgtb[MM];
    __shared__ int    slab[MM];
    __shared__ float  svc[CC];
    __shared__ float  spart[8 * 8];

    if (tid < MM) {
        sgtb[tid] = __ldg((const float4*)gtb + b * MM + tid);
        int l  = __ldg(gtl + b * MM + tid);
        slab[tid] = min(max(l, 0), CC - 1);
    }
    if (tid < CC) svc[tid] = mask_at(cm, wide, b * CC + tid) ? 1.f : 0.f;

    const int rows = min(T2, NN - tile);
    const int n = tile + tid;

    // ---- unconditional prefetch (max MLP) -----------------------------------
    unsigned long long slot = 0ull;
    float mxv = 0.f, ax = 0.f, ay = 0.f, stv = 1.f;
    float4 pbox = make_float4(0.f, 0.f, 0.f, 0.f);
    if (tid < rows) {
        slot = g_best[b * NN + n];
        mxv  = g_mx[b * NN + n];
        float2 a = __ldg((const float2*)ap + n);
        ax = a.x; ay = a.y;
        pbox = __ldg((const float4*)(pb + ((size_t)b * NN + n) * 4));
        stv  = __ldg(st + n);
        g_best[b * NN + n] = 0ull;          // reset for next graph replay
    }
    __syncthreads();   // shared tables ready

    float cnt = 0.f, cis = 0.f, dfs = 0.f, cor = 0.f, pos = 0.f, neg = 0.f, mio = 0.f;

    if (tid < rows) {
        if (slot != 0ull) {
            cnt = 1.f;
            const int mg = MM - 1 - (int)(slot & 0x3Full);
            const float4 g = sgtb[mg];
            const int ml = slab[mg];
            const float ov = iou_sel(pbox, g);
            mio = ov;
            float psv = __ldg(ps + ((size_t)b * NN + n) * CC + ml);
            pos = 1.f / (1.f + __expf(-psv));
            cor = psv * fmaxf(ov, 0.1f) * svc[ml];

            // CIoU (value-only accuracy)
            float w1 = pbox.z - pbox.x, h1 = pbox.w - pbox.y;
            float w2 = g.z - g.x,       h2 = g.w - g.y;
            float cw = fmaxf(pbox.z, g.z) - fminf(pbox.x, g.x);
            float ch = fmaxf(pbox.w, g.w) - fminf(pbox.y, g.y);
            float c2 = cw * cw + ch * ch + 1e-7f;
            float dx = g.x + g.z - pbox.x - pbox.z;
            float dy = g.y + g.w - pbox.y - pbox.w;
            float rho2 = (dx * dx + dy * dy) * 0.25f;
            float dat = atanf(w2 / (h2 + 1e-7f)) - atanf(w1 / (h1 + 1e-7f));
            float v   = 0.40528473456935108577f * dat * dat;  // 4/pi^2
            float alp = v / (v - ov + 1.0f + 1e-7f);
            cis = 1.f - (ov - (rho2 / c2 + v * alp));

            // DFL
            float dar[4] = { (ax - g.x) / stv, (ay - g.y) / stv,
                             (g.z - ax) / stv, (g.w - ay) / stv };
            const float* bdp = bd + ((size_t)b * NN + n) * 64;
            const float4* bq = (const float4*)bdp;
#pragma unroll
            for (int sd = 0; sd < 4; sd++) {
                float4 q0 = __ldg(bq + sd * 4 + 0);
                float4 q1 = __ldg(bq + sd * 4 + 1);
                float4 q2 = __ldg(bq + sd * 4 + 2);
                float4 q3 = __ldg(bq + sd * 4 + 3);
                float mv = q0.x;
                mv = fmaxf(mv, q0.y); mv = fmaxf(mv, q0.z); mv = fmaxf(mv, q0.w);
                mv = fmaxf(mv, q1.x); mv = fmaxf(mv, q1.y); mv = fmaxf(mv, q1.z); mv = fmaxf(mv, q1.w);
                mv = fmaxf(mv, q2.x); mv = fmaxf(mv, q2.y); mv = fmaxf(mv, q2.z); mv = fmaxf(mv, q2.w);
                mv = fmaxf(mv, q3.x); mv = fmaxf(mv, q3.y); mv = fmaxf(mv, q3.z); mv = fmaxf(mv, q3.w);
                float se = __expf(q0.x - mv) + __expf(q0.y - mv) + __expf(q0.z - mv) + __expf(q0.w - mv)
                         + __expf(q1.x - mv) + __expf(q1.y - mv) + __expf(q1.z - mv) + __expf(q1.w - mv)
                         + __expf(q2.x - mv) + __expf(q2.y - mv) + __expf(q2.z - mv) + __expf(q2.w - mv)
                         + __expf(q3.x - mv) + __expf(q3.y - mv) + __expf(q3.z - mv) + __expf(q3.w - mv);
                float lse = mv + __logf(se);
                float d = fminf(fmaxf(dar[sd], 0.f), 14.99f);
                int tl = (int)d;
                int tr = min(tl + 1, RR - 1);
                float wl = (float)tr - d;
                float wr = 1.f - wl;
                float vtl = __ldg(bdp + sd * 16 + tl);
                float vtr = __ldg(bdp + sd * 16 + tr);
                dfs += (lse - vtl) * wl + (lse - vtr) * wr;
            }
        } else {
            neg = mxv;
        }
    }

    // ---- block reduction -> one plain store ---------------------------------
    float v[8] = {cnt, cis, dfs, cor, pos, neg, mio, 0.f};
#pragma unroll
    for (int k = 0; k < 7; k++) {
#pragma unroll
        for (int off = 16; off > 0; off >>= 1)
            v[k] += __shfl_down_sync(0xFFFFFFFFu, v[k], off);
    }
    if (lane == 0) {
#pragma unroll
        for (int k = 0; k < 8; k++) spart[warp * 8 + k] = v[k];
    }
    __syncthreads();
    if (tid == 0) {
        float* o = &g_p2[((size_t)b * NB2 + blockIdx.x) * 8];
#pragma unroll
        for (int k = 0; k < 8; k++) {
            float acc = 0.f;
#pragma unroll
            for (int w = 0; w < 8; w++) acc += spart[w * 8 + k];
            o[k] = acc;
        }
    }
}

// ---------------- K3: finalize (separate kernel; one warp per b) -------------
__global__ void __launch_bounds__(512)
k_final(const unsigned char* __restrict__ cm, float* __restrict__ out) {
    const int warp = threadIdx.x >> 5, lane = threadIdx.x & 31;
    const int b = warp;   // 16 warps
    const bool wide = (cm[1] == 0);
    __shared__ float s_match[BB], s_iou[BB], s_dfl[BB], s_cnt[BB], s_pos[BB], s_neg[BB], s_mio[BB];

    float w[7] = {0.f, 0.f, 0.f, 0.f, 0.f, 0.f, 0.f};
    for (int i = lane; i < NB2; i += 32) {
        const float* p = &g_p2[((size_t)b * NB2 + i) * 8];
#pragma unroll
        for (int k = 0; k < 7; k++) w[k] += p[k];
    }
    float spb = 0.f;
    for (int i = lane; i < NBSP; i += 32) spb += g_spb[b * NBSP + i];
    float vcs = 0.f;
    for (int c = lane; c < CC; c += 32)
        vcs += mask_at(cm, wide, b * CC + c) ? 1.f : 0.f;
#pragma unroll
    for (int off = 16; off > 0; off >>= 1) {
#pragma unroll
        for (int k = 0; k < 7; k++) w[k] += __shfl_down_sync(0xFFFFFFFFu, w[k], off);
        spb += __shfl_down_sync(0xFFFFFFFFu, spb, off);
        vcs += __shfl_down_sync(0xFFFFFFFFu, vcs, off);
    }
    if (lane == 0) {
        float cb = w[0];
        s_match[b] = (spb - w[3]) / ((float)NN * fmaxf(vcs, 1.f));
        s_iou[b]   = (cb > 0.f) ? w[1] / fmaxf(cb, 1.f) : 0.f;
        s_dfl[b]   = (cb > 0.f) ? w[2] / fmaxf(cb * 4.f, 1.f) : 0.f;
        s_cnt[b] = cb; s_pos[b] = w[4]; s_neg[b] = w[5]; s_mio[b] = w[6];
    }
    __syncthreads();
    if (threadIdx.x == 0) {
        float tm = 0.f, ti = 0.f, td = 0.f, tc = 0.f, tp = 0.f, tn = 0.f, tmi = 0.f;
        for (int i = 0; i < BB; i++) {
            tm += s_match[i]; ti += s_iou[i]; td += s_dfl[i];
            tc += s_cnt[i];  tp += s_pos[i]; tn += s_neg[i]; tmi += s_mio[i];
        }
        float tot_neg = (float)BB * (float)NN - tc;
        out[0] = (0.5f * tm + 7.5f * ti + 1.5f * td) / (float)BB;
        out[1] = tm / (float)BB;
        out[2] = ti / (float)BB;
        out[3] = td / (float)BB;
        out[4] = tc;
        out[5] = tp / fmaxf(tc, 1.f);
        out[6] = tn / fmaxf(tot_neg, 1.f);
        out[7] = tmi / fmaxf(tc, 1.f);
    }
}

// ---------------- launch -----------------------------------------------------
extern "C" void kernel_launch(void* const* d_in, const int* in_sizes, int n_in,
                              void* d_out, int out_size) {
    const float*         ps  = (const float*)d_in[0];          // (B,N,C)
    const float*         pbx = (const float*)d_in[1];          // (B,N,4)
    const float*         ap  = (const float*)d_in[2];          // (N,2)
    const float*         st  = (const float*)d_in[3];          // (N,1)
    const float*         bd  = (const float*)d_in[4];          // (B,N,64)
    const float*         gtb = (const float*)d_in[5];          // (B,M,4)
    const int*           gtl = (const int*)d_in[6];            // (B,M)
    const unsigned char* cm  = (const unsigned char*)d_in[7];  // (B,C) bool (dtype detected)
    float*               out = (float*)d_out;                  // 8 scalars

    k_pre<<<NTHR + BB * NBSP, 256>>>(ps, pbx, gtl, gtb, cm);
    dim3 gb(NB2, BB);
    k_main<<<gb, T2>>>(ps, pbx, ap, st, gtl, gtb, bd, cm);
    k_final<<<1, 512>>>(cm, out);
}

// round 17
// speedup vs baseline: 1.1264x; 1.1264x over previous
#include <cuda_runtime.h>
#include <cuda_bf16.h>
#include <math.h>

// Problem constants (fixed by setup_inputs)
#define BB 16
#define NN 8400
#define CC 80
#define MM 64
#define RR 16
#define KTOP 13
#define NEG_INFF (-1e30f)

static constexpr int NBA   = BB * MM / 8;             // 128 role-A blocks (8 warps = 8 pairs)
static constexpr int RPB   = 64;                      // rows per softplus block
static constexpr int NBSP  = (NN + RPB - 1) / RPB;    // 132 softplus blocks per b
static constexpr int T2    = 256;                     // threads/anchors per main block
static constexpr int NB2   = (NN + T2 - 1) / T2;      // 33

// ---------------- scratch (static device globals; no allocations) ----------
__device__ unsigned long long g_best[BB * NN];        // (align_bits<<32)|(63-m); 0 = no fg
__device__ float              g_mx[BB * NN];          // sigmoid(max valid logit) or NEG_INF
__device__ float              g_spb[BB * NBSP];       // per-block softplus partials
__device__ float              g_p2[BB * NB2 * 8];     // per-block loss partials

// ---------------- bit-exact helpers (selection path) -------------------------
__device__ __forceinline__ float iou_sel(float4 a, float4 b) {
    float x1 = fmaxf(a.x, b.x), y1 = fmaxf(a.y, b.y);
    float x2 = fminf(a.z, b.z), y2 = fminf(a.w, b.w);
    float iw = fmaxf(__fsub_rn(x2, x1), 0.f);
    float ih = fmaxf(__fsub_rn(y2, y1), 0.f);
    float inter = __fmul_rn(iw, ih);
    float a1 = __fmul_rn(__fsub_rn(a.z, a.x), __fsub_rn(a.w, a.y));
    float a2 = __fmul_rn(__fsub_rn(b.z, b.x), __fsub_rn(b.w, b.y));
    float den = __fadd_rn(__fsub_rn(__fadd_rn(a1, a2), inter), 1e-7f);
    return __fdiv_rn(inter, den);
}

__device__ __forceinline__ float sigmoid_sel(float x) {
    return __fdiv_rn(1.f, __fadd_rn(1.f, expf(-x)));
}

__device__ __forceinline__ float align_sel(float cls, float iou) {
    float i2 = __fmul_rn(iou, iou);
    float i4 = __fmul_rn(i2, i2);
    float i6 = __fmul_rn(i4, i2);
    return __fmul_rn(cls, i6);
}

// Sortable key matching jax.lax.top_k semantics: value desc, index asc on ties.
__device__ __forceinline__ unsigned long long pack_key(float v, int n) {
    unsigned int u = __float_as_uint(v);
    u = (u & 0x80000000u) ? ~u : (u | 0x80000000u);
    return ((unsigned long long)u << 32) | (unsigned int)(0xFFFFFFFFu - (unsigned int)n);
}

__device__ __forceinline__ bool mask_at(const unsigned char* cm, bool wide, int idx) {
    return wide ? (((const unsigned int*)cm)[idx] != 0u) : (cm[idx] != 0);
}

__device__ __forceinline__ unsigned long long umax64(unsigned long long a, unsigned long long b) {
    return a > b ? a : b;
}

__device__ __forceinline__ float ex2a(float x) {
    float r; asm("ex2.approx.ftz.f32 %0, %1;" : "=f"(r) : "f"(x)); return r;
}
__device__ __forceinline__ float lg2a(float x) {
    float r; asm("lg2.approx.ftz.f32 %0, %1;" : "=f"(r) : "f"(x)); return r;
}

// ---------------- K1: warp-per-(b,m) top13+scatter (A) | softplus (B) --------
__global__ void __launch_bounds__(256)
k_pre(const float* __restrict__ ps, const float* __restrict__ pb,
      const int* __restrict__ gtl, const float* __restrict__ gtb,
      const unsigned char* __restrict__ cm) {
    const int tid = threadIdx.x, lane = tid & 31, warp = tid >> 5;
    const float L2E = 1.4426950408889634f;
    const bool wide = (cm[1] == 0);

    if (blockIdx.x < NBA) {
        // ====== role A: one warp per (b,m); register top-13 + fused scatter ==
        const int pair = blockIdx.x * 8 + warp;          // 0..1023
        const int b = pair >> 6, m = pair & 63;

        const float4 bx = __ldg((const float4*)gtb + b * MM + m);
        const int l  = __ldg(gtl + b * MM + m);
        const int lc = min(max(l, 0), CC - 1);
        const bool valid = (l >= 0 && l < CC && mask_at(cm, wide, b * CC + lc));

        unsigned long long list[KTOP];
#pragma unroll
        for (int i = 0; i < KTOP; i++) list[i] = 0ull;

        if (valid) {
            const int   nsL[3]  = {80, 40, 20};
            const float ssL[3]  = {8.f, 16.f, 32.f};
            const int   offL[3] = {0, 6400, 8000};
#pragma unroll
            for (int lv = 0; lv < 3; lv++) {
                const int nl = nsL[lv]; const float sl = ssL[lv];
                int x0 = max(0,      (int)floorf(bx.x / sl - 0.5f) - 1);
                int x1 = min(nl - 1, (int)ceilf (bx.z / sl - 0.5f) + 1);
                int y0 = max(0,      (int)floorf(bx.y / sl - 0.5f) - 1);
                int y1 = min(nl - 1, (int)ceilf (bx.w / sl - 0.5f) + 1);
                int cw = x1 - x0 + 1, chh = y1 - y0 + 1;
                if (cw <= 0 || chh <= 0) continue;      // warp-uniform
                const int tot = cw * chh;
                for (int j = lane; j < tot; j += 32) {
                    int iy = j / cw, ix = j - iy * cw;
                    float ax = (x0 + ix + 0.5f) * sl;   // bit-identical anchor grid
                    float ay = (y0 + iy + 0.5f) * sl;
                    if (ax >= bx.x && ax <= bx.z && ay >= bx.y && ay <= bx.w) {
                        int n = offL[lv] + (y0 + iy) * nl + (x0 + ix);
                        float4 pbox = __ldg((const float4*)(pb + ((size_t)b * NN + n) * 4));
                        float cls = sigmoid_sel(__ldg(ps + ((size_t)b * NN + n) * CC + lc));
                        unsigned long long key = pack_key(align_sel(cls, iou_sel(pbox, bx)), n);
                        if (key > list[KTOP - 1]) {
#pragma unroll
                            for (int i = 0; i < KTOP; i++) {
                                if (key > list[i]) {
                                    unsigned long long t = list[i]; list[i] = key; key = t;
                                }
                            }
                        }
                    }
                }
            }
        }

        // 13 extraction rounds; leader scatters each extracted key directly.
        const unsigned long long mtag = (unsigned long long)(MM - 1 - m);
        for (int r = 0; r < KTOP; r++) {
            unsigned long long cur = list[0];
            unsigned long long mx = cur;
#pragma unroll
            for (int o = 16; o; o >>= 1)
                mx = umax64(mx, __shfl_xor_sync(0xFFFFFFFFu, mx, o));
            if (mx == 0ull) break;                       // <13 candidates: done
            unsigned int bal = __ballot_sync(0xFFFFFFFFu, cur == mx);
            int leader = __ffs(bal) - 1;
            if (lane == leader) {
                unsigned int n = 0xFFFFFFFFu - (unsigned int)(mx & 0xFFFFFFFFu);
                atomicMax(&g_best[b * NN + n], (mx & 0xFFFFFFFF00000000ull) | mtag);
#pragma unroll
                for (int i = 0; i < KTOP - 1; i++) list[i] = list[i + 1];
                list[KTOP - 1] = 0ull;
            }
        }
    } else {
        // ========== role B: coalesced softplus sum + per-row valid max =======
        __shared__ float svcB[CC];
        __shared__ int   sAllv, sAnyv;
        __shared__ float spw[8];

        const int i = blockIdx.x - NBA;
        const int b = i / NBSP, blk = i - b * NBSP;
        const int row0 = blk * RPB;
        const int rend = min(row0 + RPB, NN);

        if (tid < CC) svcB[tid] = mask_at(cm, wide, b * CC + tid) ? 1.f : 0.f;
        __syncthreads();
        if (tid == 0) {
            float vs = 0.f;
            for (int cc = 0; cc < CC; cc++) vs += svcB[cc];
            sAllv = (vs == (float)CC) ? 1 : 0;
            sAnyv = (vs > 0.f) ? 1 : 0;
        }
        __syncthreads();

        const int r     = row0 + warp * 8 + (lane >> 2);
        const int chunk = lane & 3;
        float sp_l = 0.f, tmax_l = -3.4e38f;
        if (r < rend) {
            const float4* p = (const float4*)(ps + ((size_t)b * NN + r) * CC) + chunk * 5;
            if (sAllv) {
#pragma unroll
                for (int j = 0; j < 5; j++) {
                    float4 q = __ldg(p + j);
                    float t;
                    t = q.x * L2E; sp_l += fmaxf(t, 0.f) + lg2a(1.f + ex2a(-fabsf(t))); tmax_l = fmaxf(tmax_l, t);
                    t = q.y * L2E; sp_l += fmaxf(t, 0.f) + lg2a(1.f + ex2a(-fabsf(t))); tmax_l = fmaxf(tmax_l, t);
                    t = q.z * L2E; sp_l += fmaxf(t, 0.f) + lg2a(1.f + ex2a(-fabsf(t))); tmax_l = fmaxf(tmax_l, t);
                    t = q.w * L2E; sp_l += fmaxf(t, 0.f) + lg2a(1.f + ex2a(-fabsf(t))); tmax_l = fmaxf(tmax_l, t);
                }
            } else {
                const float* vv = &svcB[chunk * 20];
#pragma unroll
                for (int j = 0; j < 5; j++) {
                    float4 q = __ldg(p + j);
                    float t;
                    t = q.x * L2E; sp_l += vv[j*4+0] * (fmaxf(t, 0.f) + lg2a(1.f + ex2a(-fabsf(t)))); tmax_l = fmaxf(tmax_l, vv[j*4+0] != 0.f ? t : -3.4e38f);
                    t = q.y * L2E; sp_l += vv[j*4+1] * (fmaxf(t, 0.f) + lg2a(1.f + ex2a(-fabsf(t)))); tmax_l = fmaxf(tmax_l, vv[j*4+1] != 0.f ? t : -3.4e38f);
                    t = q.z * L2E; sp_l += vv[j*4+2] * (fmaxf(t, 0.f) + lg2a(1.f + ex2a(-fabsf(t)))); tmax_l = fmaxf(tmax_l, vv[j*4+2] != 0.f ? t : -3.4e38f);
                    t = q.w * L2E; sp_l += vv[j*4+3] * (fmaxf(t, 0.f) + lg2a(1.f + ex2a(-fabsf(t)))); tmax_l = fmaxf(tmax_l, vv[j*4+3] != 0.f ? t : -3.4e38f);
                }
            }
        }
        float tm = fmaxf(tmax_l, __shfl_xor_sync(0xFFFFFFFFu, tmax_l, 1));
        tm = fmaxf(tm, __shfl_xor_sync(0xFFFFFFFFu, tm, 2));
        if (chunk == 0 && r < rend)
            g_mx[b * NN + r] = sAnyv ? (1.f / (1.f + ex2a(-tm))) : NEG_INFF;

        float s = sp_l;
#pragma unroll
        for (int o = 16; o; o >>= 1) s += __shfl_down_sync(0xFFFFFFFFu, s, o);
        if (lane == 0) spw[warp] = s;
        __syncthreads();
        if (tid == 0) {
            float tot = 0.f;
#pragma unroll
            for (int w = 0; w < 8; w++) tot += spw[w];
            g_spb[i] = tot * (1.f / L2E);
        }
    }
}

// ---------------- K2: per-anchor fg losses (NO completion protocol) ----------
__global__ void __launch_bounds__(T2)
k_main(const float* __restrict__ ps, const float* __restrict__ pb,
       const float* __restrict__ ap, const float* __restrict__ st,
       const int* __restrict__ gtl, const float* __restrict__ gtb,
       const float* __restrict__ bd, const unsigned char* __restrict__ cm) {
    const int b    = blockIdx.y;
    const int tile = blockIdx.x * T2;
    const int tid  = threadIdx.x;
    const int warp = tid >> 5, lane = tid & 31;
    const bool wide = (cm[1] == 0);

    __shared__ float4 sgtb[MM];
    __shared__ int    slab[MM];
    __shared__ float  svc[CC];
    __shared__ float  spart[8 * 8];

    if (tid < MM) {
        sgtb[tid] = __ldg((const float4*)gtb + b * MM + tid);
        int l  = __ldg(gtl + b * MM + tid);
        slab[tid] = min(max(l, 0), CC - 1);
    }
    if (tid < CC) svc[tid] = mask_at(cm, wide, b * CC + tid) ? 1.f : 0.f;

    const int rows = min(T2, NN - tile);
    const int n = tile + tid;

    // ---- unconditional prefetch (max MLP) -----------------------------------
    unsigned long long slot = 0ull;
    float mxv = 0.f, ax = 0.f, ay = 0.f, stv = 1.f;
    float4 pbox = make_float4(0.f, 0.f, 0.f, 0.f);
    if (tid < rows) {
        slot = g_best[b * NN + n];
        mxv  = g_mx[b * NN + n];
        float2 a = __ldg((const float2*)ap + n);
        ax = a.x; ay = a.y;
        pbox = __ldg((const float4*)(pb + ((size_t)b * NN + n) * 4));
        stv  = __ldg(st + n);
        g_best[b * NN + n] = 0ull;          // reset for next graph replay
    }
    __syncthreads();   // shared tables ready

    float cnt = 0.f, cis = 0.f, dfs = 0.f, cor = 0.f, pos = 0.f, neg = 0.f, mio = 0.f;

    if (tid < rows) {
        if (slot != 0ull) {
            cnt = 1.f;
            const int mg = MM - 1 - (int)(slot & 0x3Full);
            const float4 g = sgtb[mg];
            const int ml = slab[mg];
            const float ov = iou_sel(pbox, g);
            mio = ov;
            float psv = __ldg(ps + ((size_t)b * NN + n) * CC + ml);
            pos = 1.f / (1.f + __expf(-psv));
            cor = psv * fmaxf(ov, 0.1f) * svc[ml];

            // CIoU (value-only accuracy)
            float w1 = pbox.z - pbox.x, h1 = pbox.w - pbox.y;
            float w2 = g.z - g.x,       h2 = g.w - g.y;
            float cw = fmaxf(pbox.z, g.z) - fminf(pbox.x, g.x);
            float ch = fmaxf(pbox.w, g.w) - fminf(pbox.y, g.y);
            float c2 = cw * cw + ch * ch + 1e-7f;
            float dx = g.x + g.z - pbox.x - pbox.z;
            float dy = g.y + g.w - pbox.y - pbox.w;
            float rho2 = (dx * dx + dy * dy) * 0.25f;
            float dat = atanf(w2 / (h2 + 1e-7f)) - atanf(w1 / (h1 + 1e-7f));
            float v   = 0.40528473456935108577f * dat * dat;  // 4/pi^2
            float alp = v / (v - ov + 1.0f + 1e-7f);
            cis = 1.f - (ov - (rho2 / c2 + v * alp));

            // DFL
            float dar[4] = { (ax - g.x) / stv, (ay - g.y) / stv,
                             (g.z - ax) / stv, (g.w - ay) / stv };
            const float* bdp = bd + ((size_t)b * NN + n) * 64;
            const float4* bq = (const float4*)bdp;
#pragma unroll
            for (int sd = 0; sd < 4; sd++) {
                float4 q0 = __ldg(bq + sd * 4 + 0);
                float4 q1 = __ldg(bq + sd * 4 + 1);
                float4 q2 = __ldg(bq + sd * 4 + 2);
                float4 q3 = __ldg(bq + sd * 4 + 3);
                float mv = q0.x;
                mv = fmaxf(mv, q0.y); mv = fmaxf(mv, q0.z); mv = fmaxf(mv, q0.w);
                mv = fmaxf(mv, q1.x); mv = fmaxf(mv, q1.y); mv = fmaxf(mv, q1.z); mv = fmaxf(mv, q1.w);
                mv = fmaxf(mv, q2.x); mv = fmaxf(mv, q2.y); mv = fmaxf(mv, q2.z); mv = fmaxf(mv, q2.w);
                mv = fmaxf(mv, q3.x); mv = fmaxf(mv, q3.y); mv = fmaxf(mv, q3.z); mv = fmaxf(mv, q3.w);
                float se = __expf(q0.x - mv) + __expf(q0.y - mv) + __expf(q0.z - mv) + __expf(q0.w - mv)
                         + __expf(q1.x - mv) + __expf(q1.y - mv) + __expf(q1.z - mv) + __expf(q1.w - mv)
                         + __expf(q2.x - mv) + __expf(q2.y - mv) + __expf(q2.z - mv) + __expf(q2.w - mv)
                         + __expf(q3.x - mv) + __expf(q3.y - mv) + __expf(q3.z - mv) + __expf(q3.w - mv);
                float lse = mv + __logf(se);
                float d = fminf(fmaxf(dar[sd], 0.f), 14.99f);
                int tl = (int)d;
                int tr = min(tl + 1, RR - 1);
                float wl = (float)tr - d;
                float wr = 1.f - wl;
                float vtl = __ldg(bdp + sd * 16 + tl);
                float vtr = __ldg(bdp + sd * 16 + tr);
                dfs += (lse - vtl) * wl + (lse - vtr) * wr;
            }
        } else {
            neg = mxv;
        }
    }

    // ---- block reduction -> one plain store ---------------------------------
    float v[8] = {cnt, cis, dfs, cor, pos, neg, mio, 0.f};
#pragma unroll
    for (int k = 0; k < 7; k++) {
#pragma unroll
        for (int off = 16; off > 0; off >>= 1)
            v[k] += __shfl_down_sync(0xFFFFFFFFu, v[k], off);
    }
    if (lane == 0) {
#pragma unroll
        for (int k = 0; k < 8; k++) spart[warp * 8 + k] = v[k];
    }
    __syncthreads();
    if (tid == 0) {
        float* o = &g_p2[((size_t)b * NB2 + blockIdx.x) * 8];
#pragma unroll
        for (int k = 0; k < 8; k++) {
            float acc = 0.f;
#pragma unroll
            for (int w = 0; w < 8; w++) acc += spart[w * 8 + k];
            o[k] = acc;
        }
    }
}

// ---------------- K3: finalize (separate kernel; one warp per b) -------------
__global__ void __launch_bounds__(512)
k_final(const unsigned char* __restrict__ cm, float* __restrict__ out) {
    const int warp = threadIdx.x >> 5, lane = threadIdx.x & 31;
    const int b = warp;   // 16 warps
    const bool wide = (cm[1] == 0);
    __shared__ float s_match[BB], s_iou[BB], s_dfl[BB], s_cnt[BB], s_pos[BB], s_neg[BB], s_mio[BB];

    float w[7] = {0.f, 0.f, 0.f, 0.f, 0.f, 0.f, 0.f};
    for (int i = lane; i < NB2; i += 32) {
        const float* p = &g_p2[((size_t)b * NB2 + i) * 8];
#pragma unroll
        for (int k = 0; k < 7; k++) w[k] += p[k];
    }
    float spb = 0.f;
    for (int i = lane; i < NBSP; i += 32) spb += g_spb[b * NBSP + i];
    float vcs = 0.f;
    for (int c = lane; c < CC; c += 32)
        vcs += mask_at(cm, wide, b * CC + c) ? 1.f : 0.f;
#pragma unroll
    for (int off = 16; off > 0; off >>= 1) {
#pragma unroll
        for (int k = 0; k < 7; k++) w[k] += __shfl_down_sync(0xFFFFFFFFu, w[k], off);
        spb += __shfl_down_sync(0xFFFFFFFFu, spb, off);
        vcs += __shfl_down_sync(0xFFFFFFFFu, vcs, off);
    }
    if (lane == 0) {
        float cb = w[0];
        s_match[b] = (spb - w[3]) / ((float)NN * fmaxf(vcs, 1.f));
        s_iou[b]   = (cb > 0.f) ? w[1] / fmaxf(cb, 1.f) : 0.f;
        s_dfl[b]   = (cb > 0.f) ? w[2] / fmaxf(cb * 4.f, 1.f) : 0.f;
        s_cnt[b] = cb; s_pos[b] = w[4]; s_neg[b] = w[5]; s_mio[b] = w[6];
    }
    __syncthreads();
    if (threadIdx.x == 0) {
        float tm = 0.f, ti = 0.f, td = 0.f, tc = 0.f, tp = 0.f, tn = 0.f, tmi = 0.f;
        for (int i = 0; i < BB; i++) {
            tm += s_match[i]; ti += s_iou[i]; td += s_dfl[i];
            tc += s_cnt[i];  tp += s_pos[i]; tn += s_neg[i]; tmi += s_mio[i];
        }
        float tot_neg = (float)BB * (float)NN - tc;
        out[0] = (0.5f * tm + 7.5f * ti + 1.5f * td) / (float)BB;
        out[1] = tm / (float)BB;
        out[2] = ti / (float)BB;
        out[3] = td / (float)BB;
        out[4] = tc;
        out[5] = tp / fmaxf(tc, 1.f);
        out[6] = tn / fmaxf(tot_neg, 1.f);
        out[7] = tmi / fmaxf(tc, 1.f);
    }
}

// ---------------- launch -----------------------------------------------------
extern "C" void kernel_launch(void* const* d_in, const int* in_sizes, int n_in,
                              void* d_out, int out_size) {
    const float*         ps  = (const float*)d_in[0];          // (B,N,C)
    const float*         pbx = (const float*)d_in[1];          // (B,N,4)
    const float*         ap  = (const float*)d_in[2];          // (N,2)
    const float*         st  = (const float*)d_in[3];          // (N,1)
    const float*         bd  = (const float*)d_in[4];          // (B,N,64)
    const float*         gtb = (const float*)d_in[5];          // (B,M,4)
    const int*           gtl = (const int*)d_in[6];            // (B,M)
    const unsigned char* cm  = (const unsigned char*)d_in[7];  // (B,C) bool (dtype detected)
    float*               out = (float*)d_out;                  // 8 scalars

    k_pre<<<NBA + BB * NBSP, 256>>>(ps, pbx, gtl, gtb, cm);
    dim3 gb(NB2, BB);
    k_main<<<gb, T2>>>(ps, pbx, ap, st, gtl, gtb, bd, cm);
    k_final<<<1, 512>>>(cm, out);
}